// round 1
// baseline (speedup 1.0000x reference)
#include <cuda_runtime.h>
#include <cuda_bf16.h>
#include <cstdint>

// Problem constants
#define BB 16
#define N1 4096
#define N2 1024
#define C1 128
#define C2 256
#define DIN 384      // C2 + C1
#define DOUT 256
#define NQ (BB * N1) // 65536 total queries

// Scratch (device globals — no cudaMalloc allowed)
__device__ int   g_idx[NQ * 3];
__device__ float g_w[NQ * 3];
__device__ float g_X[(size_t)NQ * DIN];   // concat(interp, feat1)
__device__ float g_H[(size_t)NQ * DOUT];  // hidden after GEMM1+relu

// ---------------------------------------------------------------------------
// Kernel 1: 3-NN over N2=1024 candidates per query. One thread per query.
// xyz2 slice for the batch cached in SMEM (12 KB). Exact same arithmetic as
// reference: d = (dx)^2 + (dy)^2 + (dz)^2 (no dot-product cancellation).
// ---------------------------------------------------------------------------
__global__ void knn_kernel(const float* __restrict__ xyz1,
                           const float* __restrict__ xyz2) {
    __shared__ float px[N2], py[N2], pz[N2];
    const int b = blockIdx.x >> 4;              // 16 blocks per batch
    const int qbase = (blockIdx.x & 15) * 256;

    const float* x2 = xyz2 + (size_t)b * N2 * 3;
    for (int j = threadIdx.x; j < N2; j += 256) {
        px[j] = x2[j * 3 + 0];
        py[j] = x2[j * 3 + 1];
        pz[j] = x2[j * 3 + 2];
    }
    __syncthreads();

    const int q = b * N1 + qbase + threadIdx.x; // global query id
    const float* xq = xyz1 + (size_t)q * 3;
    const float qx = xq[0], qy = xq[1], qz = xq[2];

    float b0 = 3.4e38f, b1 = 3.4e38f, b2 = 3.4e38f;
    int   i0 = 0, i1 = 0, i2 = 0;

#pragma unroll 4
    for (int j = 0; j < N2; j++) {
        float dx = qx - px[j];
        float dy = qy - py[j];
        float dz = qz - pz[j];
        float d = dx * dx + dy * dy + dz * dz;
        if (d < b2) {
            if (d < b1) {
                if (d < b0) {
                    b2 = b1; i2 = i1;
                    b1 = b0; i1 = i0;
                    b0 = d;  i0 = j;
                } else {
                    b2 = b1; i2 = i1;
                    b1 = d;  i1 = j;
                }
            } else {
                b2 = d; i2 = j;
            }
        }
    }

    float d0 = fmaxf(b0, 1e-10f);
    float d1 = fmaxf(b1, 1e-10f);
    float d2 = fmaxf(b2, 1e-10f);
    float w0 = 1.0f / d0, w1 = 1.0f / d1, w2 = 1.0f / d2;
    float inv = 1.0f / (w0 + w1 + w2);

    g_idx[q * 3 + 0] = i0;
    g_idx[q * 3 + 1] = i1;
    g_idx[q * 3 + 2] = i2;
    g_w[q * 3 + 0] = w0 * inv;
    g_w[q * 3 + 1] = w1 * inv;
    g_w[q * 3 + 2] = w2 * inv;
}

// ---------------------------------------------------------------------------
// Kernel 2: weighted gather of feat2 rows + concat feat1 -> X[NQ, 384].
// One warp per query, float4 vectorized, coalesced across lanes.
// ---------------------------------------------------------------------------
__global__ void interp_concat_kernel(const float* __restrict__ feat1,
                                     const float* __restrict__ feat2) {
    const int warp = blockIdx.x * 8 + (threadIdx.x >> 5);
    const int lane = threadIdx.x & 31;
    if (warp >= NQ) return;

    const int q = warp;
    const int b = q / N1;

    const int i0 = g_idx[q * 3 + 0];
    const int i1 = g_idx[q * 3 + 1];
    const int i2 = g_idx[q * 3 + 2];
    const float w0 = g_w[q * 3 + 0];
    const float w1 = g_w[q * 3 + 1];
    const float w2 = g_w[q * 3 + 2];

    const float4* f2 = (const float4*)(feat2 + (size_t)b * N2 * C2);
    const float4* r0 = f2 + (size_t)i0 * (C2 / 4);
    const float4* r1 = f2 + (size_t)i1 * (C2 / 4);
    const float4* r2 = f2 + (size_t)i2 * (C2 / 4);
    float4* xrow = (float4*)(g_X + (size_t)q * DIN);

#pragma unroll
    for (int c = lane; c < C2 / 4; c += 32) {   // 64 float4 -> 2 per lane
        float4 a = r0[c], bv = r1[c], cv = r2[c];
        float4 o;
        o.x = w0 * a.x + w1 * bv.x + w2 * cv.x;
        o.y = w0 * a.y + w1 * bv.y + w2 * cv.y;
        o.z = w0 * a.z + w1 * bv.z + w2 * cv.z;
        o.w = w0 * a.w + w1 * bv.w + w2 * cv.w;
        xrow[c] = o;
    }

    const float4* f1 = (const float4*)(feat1 + (size_t)q * C1);
#pragma unroll
    for (int c = lane; c < C1 / 4; c += 32) {   // 32 float4 -> 1 per lane
        xrow[C2 / 4 + c] = f1[c];
    }
}

// ---------------------------------------------------------------------------
// Kernel 3/4: fp32 SGEMM 128x128 tile, BK=8, 256 threads, 8x8 per-thread,
// fused bias + ReLU. C[M,N] = relu(A[M,K] @ W[K,N] + bias). M,N,K all
// multiples of tile dims for this problem (no bounds checks needed).
// ---------------------------------------------------------------------------
__global__ __launch_bounds__(256) void sgemm_bias_relu(
    const float* __restrict__ A, const float* __restrict__ W,
    const float* __restrict__ bias, float* __restrict__ C,
    int M, int N, int K) {
    __shared__ float As[8][128];
    __shared__ float Bs[8][128];

    const int tid = threadIdx.x;
    const int tx = tid & 15;        // 0..15 -> N direction
    const int ty = tid >> 4;        // 0..15 -> M direction

    const float* Ablk = A + (size_t)blockIdx.y * 128 * K;
    const float* Wblk = W + blockIdx.x * 128;

    // A tile load: 128 rows x 8 cols = 256 float4 (2 float4 per row)
    const int arow = tid >> 1;
    const int acol = (tid & 1) * 4;
    // W tile load: 8 rows x 128 cols = 256 float4
    const int brow = tid >> 5;
    const int bcol = (tid & 31) * 4;

    float acc[8][8];
#pragma unroll
    for (int i = 0; i < 8; i++)
#pragma unroll
        for (int j = 0; j < 8; j++) acc[i][j] = 0.0f;

    for (int k0 = 0; k0 < K; k0 += 8) {
        float4 av = *(const float4*)(Ablk + (size_t)arow * K + k0 + acol);
        As[acol + 0][arow] = av.x;
        As[acol + 1][arow] = av.y;
        As[acol + 2][arow] = av.z;
        As[acol + 3][arow] = av.w;
        float4 wv = *(const float4*)(Wblk + (size_t)(k0 + brow) * N + bcol);
        *(float4*)&Bs[brow][bcol] = wv;
        __syncthreads();

#pragma unroll
        for (int k = 0; k < 8; k++) {
            float a[8], bvv[8];
            float4 a0 = *(const float4*)&As[k][ty * 8 + 0];
            float4 a1 = *(const float4*)&As[k][ty * 8 + 4];
            float4 b0 = *(const float4*)&Bs[k][tx * 8 + 0];
            float4 b1 = *(const float4*)&Bs[k][tx * 8 + 4];
            a[0] = a0.x; a[1] = a0.y; a[2] = a0.z; a[3] = a0.w;
            a[4] = a1.x; a[5] = a1.y; a[6] = a1.z; a[7] = a1.w;
            bvv[0] = b0.x; bvv[1] = b0.y; bvv[2] = b0.z; bvv[3] = b0.w;
            bvv[4] = b1.x; bvv[5] = b1.y; bvv[6] = b1.z; bvv[7] = b1.w;
#pragma unroll
            for (int i = 0; i < 8; i++)
#pragma unroll
                for (int j = 0; j < 8; j++)
                    acc[i][j] = fmaf(a[i], bvv[j], acc[i][j]);
        }
        __syncthreads();
    }

    // epilogue: bias + relu, float4 stores
    const int rowbase = blockIdx.y * 128 + ty * 8;
    const int colbase = blockIdx.x * 128 + tx * 8;
    float bsv[8];
#pragma unroll
    for (int j = 0; j < 8; j++) bsv[j] = bias[colbase + j];
#pragma unroll
    for (int i = 0; i < 8; i++) {
        float4 o0, o1;
        o0.x = fmaxf(acc[i][0] + bsv[0], 0.0f);
        o0.y = fmaxf(acc[i][1] + bsv[1], 0.0f);
        o0.z = fmaxf(acc[i][2] + bsv[2], 0.0f);
        o0.w = fmaxf(acc[i][3] + bsv[3], 0.0f);
        o1.x = fmaxf(acc[i][4] + bsv[4], 0.0f);
        o1.y = fmaxf(acc[i][5] + bsv[5], 0.0f);
        o1.z = fmaxf(acc[i][6] + bsv[6], 0.0f);
        o1.w = fmaxf(acc[i][7] + bsv[7], 0.0f);
        float* crow = C + (size_t)(rowbase + i) * N + colbase;
        *(float4*)(crow + 0) = o0;
        *(float4*)(crow + 4) = o1;
    }
}

// ---------------------------------------------------------------------------
extern "C" void kernel_launch(void* const* d_in, const int* in_sizes, int n_in,
                              void* d_out, int out_size) {
    const float* xyz1  = (const float*)d_in[0];
    const float* feat1 = (const float*)d_in[1];
    const float* xyz2  = (const float*)d_in[2];
    const float* feat2 = (const float*)d_in[3];
    const float* W1    = (const float*)d_in[4];
    const float* b1    = (const float*)d_in[5];
    const float* W2    = (const float*)d_in[6];
    const float* b2    = (const float*)d_in[7];
    float* out = (float*)d_out;

    float* X;
    float* H;
    cudaGetSymbolAddress((void**)&X, g_X);
    cudaGetSymbolAddress((void**)&H, g_H);

    // 1) 3-NN: 256 blocks x 256 threads (one thread per query)
    knn_kernel<<<BB * 16, 256>>>(xyz1, xyz2);

    // 2) interpolation + concat into X
    interp_concat_kernel<<<NQ / 8, 256>>>(feat1, feat2);

    // 3) GEMM1: [NQ,384] @ [384,256] + b1, relu -> H
    {
        dim3 grid(DOUT / 128, NQ / 128);
        sgemm_bias_relu<<<grid, 256>>>(X, W1, b1, H, NQ, DOUT, DIN);
    }
    // 4) GEMM2: [NQ,256] @ [256,256] + b2, relu -> out
    {
        dim3 grid(DOUT / 128, NQ / 128);
        sgemm_bias_relu<<<grid, 256>>>(H, W2, b2, out, NQ, DOUT, DOUT);
    }
}

// round 4
// speedup vs baseline: 3.3298x; 3.3298x over previous
#include <cuda_runtime.h>
#include <cuda_fp16.h>
#include <cuda_bf16.h>
#include <cstdint>

#define BB 16
#define N1 4096
#define N2 1024
#define C1 128
#define C2 256
#define DIN 384
#define DOUT 256
#define NQ (BB * N1)

// ---------------- device scratch (16B aligned for cp.async/uint4) --------
__device__ __align__(16) int    g_idx[NQ * 3];
__device__ __align__(16) float  g_w[NQ * 3];
__device__ __align__(16) __half g_X[(size_t)NQ * DIN];
__device__ __align__(16) __half g_H[(size_t)NQ * DOUT];
__device__ __align__(16) __half g_W1T[DOUT * DIN];
__device__ __align__(16) __half g_W2T[DOUT * DOUT];

// ---------------- PTX helpers (portable: sm_80-class, OK on compute_103) --
__device__ __forceinline__ uint32_t smem_u32(const void* p) {
    uint32_t a;
    asm("{ .reg .u64 t; cvta.to.shared.u64 t, %1; cvt.u32.u64 %0, t; }" : "=r"(a) : "l"(p));
    return a;
}
#define CP_ASYNC16(dst, src) \
    asm volatile("cp.async.cg.shared.global [%0], [%1], 16;" :: "r"(dst), "l"(src))
#define CP_COMMIT() asm volatile("cp.async.commit_group;" ::: "memory")
#define CP_WAIT(n)  asm volatile("cp.async.wait_group %0;" :: "n"(n) : "memory")

__device__ __forceinline__ void ldmatrix_x4(uint32_t* r, uint32_t addr) {
    asm volatile("ldmatrix.sync.aligned.m8n8.x4.shared.b16 {%0,%1,%2,%3}, [%4];"
                 : "=r"(r[0]), "=r"(r[1]), "=r"(r[2]), "=r"(r[3]) : "r"(addr));
}
__device__ __forceinline__ void mma16816(float* d, const uint32_t* a, const uint32_t* b) {
    asm volatile(
        "mma.sync.aligned.m16n8k16.row.col.f32.f16.f16.f32 "
        "{%0,%1,%2,%3}, {%4,%5,%6,%7}, {%8,%9}, {%0,%1,%2,%3};"
        : "+f"(d[0]), "+f"(d[1]), "+f"(d[2]), "+f"(d[3])
        : "r"(a[0]), "r"(a[1]), "r"(a[2]), "r"(a[3]), "r"(b[0]), "r"(b[1]));
}
#define SWZ(bo) ((bo) ^ (((bo) >> 3) & 0x70))

// ---------------------------------------------------------------------------
// Kernel 1: exact 3-NN, 4 threads/query (256 candidates each) + shuffle merge.
// Full-triple conditional swap (partner's 3rd only droppable AFTER the swap).
// ---------------------------------------------------------------------------
__global__ __launch_bounds__(256) void knn_kernel(const float* __restrict__ xyz1,
                                                  const float* __restrict__ xyz2) {
    __shared__ float px[N2], py[N2], pz[N2];
    const int qb = blockIdx.x * 64;
    const int b = qb >> 12;
    const float* x2 = xyz2 + (size_t)b * N2 * 3;
    for (int j = threadIdx.x; j < N2; j += 256) {
        px[j] = x2[3 * j]; py[j] = x2[3 * j + 1]; pz[j] = x2[3 * j + 2];
    }
    __syncthreads();

    const int q = qb + (threadIdx.x >> 2);
    const int sub = threadIdx.x & 3;
    const float qx = xyz1[3 * q], qy = xyz1[3 * q + 1], qz = xyz1[3 * q + 2];

    float b0 = 3.4e38f, b1 = 3.4e38f, b2 = 3.4e38f;
    int i0 = 0, i1 = 0, i2 = 0;
    const int js = sub * 256;
#pragma unroll 4
    for (int j = js; j < js + 256; j++) {
        float dx = qx - px[j], dy = qy - py[j], dz = qz - pz[j];
        float d = dx * dx + dy * dy + dz * dz;
        if (d < b2) {
            if (d < b1) {
                if (d < b0) { b2 = b1; i2 = i1; b1 = b0; i1 = i0; b0 = d; i0 = j; }
                else        { b2 = b1; i2 = i1; b1 = d; i1 = j; }
            } else { b2 = d; i2 = j; }
        }
    }
#pragma unroll
    for (int dlt = 1; dlt <= 2; dlt <<= 1) {
        float c0 = __shfl_xor_sync(0xffffffffu, b0, dlt);
        float c1 = __shfl_xor_sync(0xffffffffu, b1, dlt);
        float c2 = __shfl_xor_sync(0xffffffffu, b2, dlt);
        int k0 = __shfl_xor_sync(0xffffffffu, i0, dlt);
        int k1 = __shfl_xor_sync(0xffffffffu, i1, dlt);
        int k2 = __shfl_xor_sync(0xffffffffu, i2, dlt);
        if (c0 < b0) {          // full triple swap so b-triple stays sorted
            float tf; int ti;
            tf = b0; b0 = c0; c0 = tf; ti = i0; i0 = k0; k0 = ti;
            tf = b1; b1 = c1; c1 = tf; ti = i1; i1 = k1; k1 = ti;
            tf = b2; b2 = c2; c2 = tf; ti = i2; i2 = k2; k2 = ti;
        }
        // now b0 = global min and (c0<=c1<=c2); c2 can be at best 4th place
        if (c0 < b1) {
            if (b1 < c1) { b2 = b1; i2 = i1; } else { b2 = c1; i2 = k1; }
            b1 = c0; i1 = k0;
        } else if (c0 < b2) { b2 = c0; i2 = k0; }
        (void)c2; (void)k2;
    }
    if (sub == 0) {
        float d0 = fmaxf(b0, 1e-10f), d1 = fmaxf(b1, 1e-10f), d2 = fmaxf(b2, 1e-10f);
        float w0 = 1.0f / d0, w1 = 1.0f / d1, w2 = 1.0f / d2;
        float inv = 1.0f / (w0 + w1 + w2);
        g_idx[q * 3] = i0; g_idx[q * 3 + 1] = i1; g_idx[q * 3 + 2] = i2;
        g_w[q * 3] = w0 * inv; g_w[q * 3 + 1] = w1 * inv; g_w[q * 3 + 2] = w2 * inv;
    }
}

// ---------------------------------------------------------------------------
// Kernel 2: interpolate + concat -> X (fp16)
// ---------------------------------------------------------------------------
__device__ __forceinline__ void to_h4(float4 o, __half* p) {
    __half2 h0 = __floats2half2_rn(o.x, o.y);
    __half2 h1 = __floats2half2_rn(o.z, o.w);
    *(__half2*)p = h0; *(__half2*)(p + 2) = h1;
}

__global__ void interp_kernel(const float* __restrict__ feat1,
                              const float* __restrict__ feat2) {
    const int q = blockIdx.x * 8 + (threadIdx.x >> 5);
    const int lane = threadIdx.x & 31;
    const int b = q >> 12;
    const int i0 = g_idx[q * 3], i1 = g_idx[q * 3 + 1], i2 = g_idx[q * 3 + 2];
    const float w0 = g_w[q * 3], w1 = g_w[q * 3 + 1], w2 = g_w[q * 3 + 2];
    const float4* f2 = (const float4*)(feat2 + (size_t)b * N2 * C2);
    const float4* r0 = f2 + (size_t)i0 * (C2 / 4);
    const float4* r1 = f2 + (size_t)i1 * (C2 / 4);
    const float4* r2 = f2 + (size_t)i2 * (C2 / 4);
    __half* x = g_X + (size_t)q * DIN;
#pragma unroll
    for (int c = lane; c < C2 / 4; c += 32) {
        float4 a = r0[c], d = r1[c], e = r2[c];
        float4 o;
        o.x = w0 * a.x + w1 * d.x + w2 * e.x;
        o.y = w0 * a.y + w1 * d.y + w2 * e.y;
        o.z = w0 * a.z + w1 * d.z + w2 * e.z;
        o.w = w0 * a.w + w1 * d.w + w2 * e.w;
        to_h4(o, x + c * 4);
    }
    const float4* f1 = (const float4*)(feat1 + (size_t)q * C1);
#pragma unroll
    for (int c = lane; c < C1 / 4; c += 32)
        to_h4(f1[c], x + C2 + c * 4);
}

// ---------------------------------------------------------------------------
// Kernel 0: transpose W -> W^T fp16
// ---------------------------------------------------------------------------
__global__ void prep_w(const float* __restrict__ W1, const float* __restrict__ W2) {
    int i = blockIdx.x * 256 + threadIdx.x;
    if (i < DIN * DOUT) {
        int k = i / DOUT, n = i % DOUT;
        g_W1T[n * DIN + k] = __float2half(W1[i]);
    } else {
        int j = i - DIN * DOUT;
        if (j < DOUT * DOUT) {
            int k = j / DOUT, n = j % DOUT;
            g_W2T[n * DOUT + k] = __float2half(W2[j]);
        }
    }
}

// ---------------------------------------------------------------------------
// HGEMM: C[M,256] = relu(A[M,K] @ W + bias). A fp16 row-major, Bt = W^T fp16
// [256,K] row-major. CTA tile 128x128, BK=64, double-buffered cp.async,
// ldmatrix + mma.sync.m16n8k16, fp32 accumulate. WRITE_H: fp16 out else f32.
// ---------------------------------------------------------------------------
#define HGEMM_SMEM (2 * 32768)

template<int K, bool WRITE_H>
__global__ __launch_bounds__(256, 2) void hgemm(
    const __half* __restrict__ A, const __half* __restrict__ Bt,
    const float* __restrict__ bias,
    __half* __restrict__ outH, float* __restrict__ outF) {
    constexpr int NC = K / 64;
    extern __shared__ char smem[];
    const uint32_t sb = smem_u32(smem);
    const int tid = threadIdx.x;
    const int w = tid >> 5, lane = tid & 31;
    const int wy = w >> 2, wx = w & 3;
    const int mblk = blockIdx.y * 128, nblk = blockIdx.x * 128;

    const char* Abase = (const char*)(A + (size_t)mblk * K);
    const char* Bbase = (const char*)(Bt + (size_t)nblk * K);
    const int row_l = tid >> 3;
    const int ch_l = tid & 7;

    float acc[4][4][4];
#pragma unroll
    for (int i = 0; i < 4; i++)
#pragma unroll
        for (int j = 0; j < 4; j++)
#pragma unroll
            for (int k = 0; k < 4; k++) acc[i][j][k] = 0.0f;

    auto issue = [&](int c) {
        const uint32_t base = sb + (uint32_t)(c & 1) * 32768u;
        const char* ag = Abase + (size_t)c * 128;
        const char* bg = Bbase + (size_t)c * 128;
#pragma unroll
        for (int rr = 0; rr < 4; rr++) {
            const int row = row_l + rr * 32;
            const uint32_t off = (uint32_t)(row * 128 + ch_l * 16);
            const uint32_t d = base + SWZ(off);
            CP_ASYNC16(d, ag + (size_t)row * (K * 2) + ch_l * 16);
            CP_ASYNC16(d + 16384, bg + (size_t)row * (K * 2) + ch_l * 16);
        }
        CP_COMMIT();
    };

    issue(0);
#pragma unroll
    for (int c = 0; c < NC; c++) {
        if (c + 1 < NC) { issue(c + 1); CP_WAIT(1); }
        else            { CP_WAIT(0); }
        __syncthreads();
        const uint32_t abase = sb + (uint32_t)(c & 1) * 32768u;
        const uint32_t bbase = abase + 16384u;
#pragma unroll
        for (int ks = 0; ks < 4; ks++) {
            uint32_t af[4][4];
#pragma unroll
            for (int mt = 0; mt < 4; mt++) {
                const int row = wy * 64 + mt * 16 + ((lane >> 3) & 1) * 8 + (lane & 7);
                const int ch = ks * 2 + (lane >> 4);
                const uint32_t off = (uint32_t)(row * 128 + ch * 16);
                ldmatrix_x4(af[mt], abase + SWZ(off));
            }
            uint32_t bf[4][2];
#pragma unroll
            for (int p = 0; p < 2; p++) {
                const int t = lane >> 3;
                const int nrow = wx * 32 + (2 * p + (t >> 1)) * 8 + (lane & 7);
                const int ch = ks * 2 + (t & 1);
                const uint32_t off = (uint32_t)(nrow * 128 + ch * 16);
                uint32_t r[4];
                ldmatrix_x4(r, bbase + SWZ(off));
                bf[2 * p][0] = r[0]; bf[2 * p][1] = r[1];
                bf[2 * p + 1][0] = r[2]; bf[2 * p + 1][1] = r[3];
            }
#pragma unroll
            for (int mt = 0; mt < 4; mt++)
#pragma unroll
                for (int nt = 0; nt < 4; nt++)
                    mma16816(acc[mt][nt], af[mt], bf[nt]);
        }
        __syncthreads();
    }

#pragma unroll
    for (int mt = 0; mt < 4; mt++) {
#pragma unroll
        for (int nt = 0; nt < 4; nt++) {
            const int row0 = mblk + wy * 64 + mt * 16 + (lane >> 2);
            const int col = nblk + wx * 32 + nt * 8 + 2 * (lane & 3);
            const float bz0 = bias[col], bz1 = bias[col + 1];
            float v00 = fmaxf(acc[mt][nt][0] + bz0, 0.0f);
            float v01 = fmaxf(acc[mt][nt][1] + bz1, 0.0f);
            float v10 = fmaxf(acc[mt][nt][2] + bz0, 0.0f);
            float v11 = fmaxf(acc[mt][nt][3] + bz1, 0.0f);
            if constexpr (WRITE_H) {
                *(__half2*)(outH + (size_t)row0 * 256 + col) = __floats2half2_rn(v00, v01);
                *(__half2*)(outH + (size_t)(row0 + 8) * 256 + col) = __floats2half2_rn(v10, v11);
            } else {
                float2 o0; o0.x = v00; o0.y = v01;
                float2 o1; o1.x = v10; o1.y = v11;
                *(float2*)(outF + (size_t)row0 * 256 + col) = o0;
                *(float2*)(outF + (size_t)(row0 + 8) * 256 + col) = o1;
            }
        }
    }
}

// ---------------------------------------------------------------------------
extern "C" void kernel_launch(void* const* d_in, const int* in_sizes, int n_in,
                              void* d_out, int out_size) {
    const float* xyz1  = (const float*)d_in[0];
    const float* feat1 = (const float*)d_in[1];
    const float* xyz2  = (const float*)d_in[2];
    const float* feat2 = (const float*)d_in[3];
    const float* W1    = (const float*)d_in[4];
    const float* b1    = (const float*)d_in[5];
    const float* W2    = (const float*)d_in[6];
    const float* b2    = (const float*)d_in[7];
    float* out = (float*)d_out;

    __half *X, *H, *W1T, *W2T;
    cudaGetSymbolAddress((void**)&X, g_X);
    cudaGetSymbolAddress((void**)&H, g_H);
    cudaGetSymbolAddress((void**)&W1T, g_W1T);
    cudaGetSymbolAddress((void**)&W2T, g_W2T);

    cudaFuncSetAttribute((const void*)hgemm<DIN, true>,
                         cudaFuncAttributeMaxDynamicSharedMemorySize, HGEMM_SMEM);
    cudaFuncSetAttribute((const void*)hgemm<DOUT, false>,
                         cudaFuncAttributeMaxDynamicSharedMemorySize, HGEMM_SMEM);

    prep_w<<<(DIN * DOUT + DOUT * DOUT) / 256, 256>>>(W1, W2);
    knn_kernel<<<NQ / 64, 256>>>(xyz1, xyz2);
    interp_kernel<<<NQ / 8, 256>>>(feat1, feat2);

    dim3 grid(DOUT / 128, NQ / 128);
    hgemm<DIN, true><<<grid, 256, HGEMM_SMEM>>>(X, W1T, b1, H, nullptr);
    hgemm<DOUT, false><<<grid, 256, HGEMM_SMEM>>>(H, W2T, b2, nullptr, out);
}

// round 5
// speedup vs baseline: 4.4413x; 1.3338x over previous
#include <cuda_runtime.h>
#include <cuda_fp16.h>
#include <cuda_bf16.h>
#include <cstdint>

#define BB 16
#define N1 4096
#define N2 1024
#define C1 128
#define C2 256
#define DIN 384
#define DOUT 256
#define NQ (BB * N1)

// ---------------- device scratch ----------------
__device__ __align__(16) int    g_idx[NQ * 3];
__device__ __align__(16) float  g_w[NQ * 3];
__device__ __align__(16) __half g_X[(size_t)NQ * DIN];
__device__ __align__(16) __half g_H[(size_t)NQ * DOUT];
__device__ __align__(16) __half g_W1T[DOUT * DIN];
__device__ __align__(16) __half g_W2T[DOUT * DOUT];
__device__ __align__(16) __half g_feat2h[(size_t)BB * N2 * C2];

// ---------------- PTX helpers (portable, OK on compute_103) ----------------
__device__ __forceinline__ uint32_t smem_u32(const void* p) {
    uint32_t a;
    asm("{ .reg .u64 t; cvta.to.shared.u64 t, %1; cvt.u32.u64 %0, t; }" : "=r"(a) : "l"(p));
    return a;
}
#define CP_ASYNC16(dst, src) \
    asm volatile("cp.async.cg.shared.global [%0], [%1], 16;" :: "r"(dst), "l"(src))
#define CP_COMMIT() asm volatile("cp.async.commit_group;" ::: "memory")
#define CP_WAIT(n)  asm volatile("cp.async.wait_group %0;" :: "n"(n) : "memory")

__device__ __forceinline__ void ldmatrix_x4(uint32_t* r, uint32_t addr) {
    asm volatile("ldmatrix.sync.aligned.m8n8.x4.shared.b16 {%0,%1,%2,%3}, [%4];"
                 : "=r"(r[0]), "=r"(r[1]), "=r"(r[2]), "=r"(r[3]) : "r"(addr));
}
__device__ __forceinline__ void mma16816(float* d, const uint32_t* a, const uint32_t* b) {
    asm volatile(
        "mma.sync.aligned.m16n8k16.row.col.f32.f16.f16.f32 "
        "{%0,%1,%2,%3}, {%4,%5,%6,%7}, {%8,%9}, {%0,%1,%2,%3};"
        : "+f"(d[0]), "+f"(d[1]), "+f"(d[2]), "+f"(d[3])
        : "r"(a[0]), "r"(a[1]), "r"(a[2]), "r"(a[3]), "r"(b[0]), "r"(b[1]));
}
#define SWZ(bo) ((bo) ^ (((bo) >> 3) & 0x70))

// ---------------------------------------------------------------------------
// Kernel 1: exact 3-NN. float4 smem (1 LDS.128/candidate, conflict-free),
// interleaved sub-partition j = sub + 4*i, exact shuffle top-3 merge.
// ---------------------------------------------------------------------------
__global__ __launch_bounds__(256) void knn_kernel(const float* __restrict__ xyz1,
                                                  const float* __restrict__ xyz2) {
    __shared__ float4 pts[N2];
    const int qb = blockIdx.x * 64;
    const int b = qb >> 12;
    const float* x2 = xyz2 + (size_t)b * N2 * 3;
    for (int j = threadIdx.x; j < N2; j += 256) {
        pts[j] = make_float4(x2[3 * j], x2[3 * j + 1], x2[3 * j + 2], 0.0f);
    }
    __syncthreads();

    const int q = qb + (threadIdx.x >> 2);
    const int sub = threadIdx.x & 3;
    const float qx = xyz1[3 * q], qy = xyz1[3 * q + 1], qz = xyz1[3 * q + 2];

    float b0 = 3.4e38f, b1 = 3.4e38f, b2 = 3.4e38f;
    int i0 = 0, i1 = 0, i2 = 0;
#pragma unroll 4
    for (int i = 0; i < 256; i++) {
        const int j = sub + 4 * i;          // interleaved partition: lanes hit
        float4 p = pts[j];                  // 4 consecutive float4s -> no conflict
        float dx = qx - p.x, dy = qy - p.y, dz = qz - p.z;
        float d = dx * dx + dy * dy + dz * dz;
        if (d < b2) {
            if (d < b1) {
                if (d < b0) { b2 = b1; i2 = i1; b1 = b0; i1 = i0; b0 = d; i0 = j; }
                else        { b2 = b1; i2 = i1; b1 = d; i1 = j; }
            } else { b2 = d; i2 = j; }
        }
    }
#pragma unroll
    for (int dlt = 1; dlt <= 2; dlt <<= 1) {
        float c0 = __shfl_xor_sync(0xffffffffu, b0, dlt);
        float c1 = __shfl_xor_sync(0xffffffffu, b1, dlt);
        float c2 = __shfl_xor_sync(0xffffffffu, b2, dlt);
        int k0 = __shfl_xor_sync(0xffffffffu, i0, dlt);
        int k1 = __shfl_xor_sync(0xffffffffu, i1, dlt);
        int k2 = __shfl_xor_sync(0xffffffffu, i2, dlt);
        if (c0 < b0) {          // full triple swap so b-triple stays sorted
            float tf; int ti;
            tf = b0; b0 = c0; c0 = tf; ti = i0; i0 = k0; k0 = ti;
            tf = b1; b1 = c1; c1 = tf; ti = i1; i1 = k1; k1 = ti;
            tf = b2; b2 = c2; c2 = tf; ti = i2; i2 = k2; k2 = ti;
        }
        if (c0 < b1) {
            if (b1 < c1) { b2 = b1; i2 = i1; } else { b2 = c1; i2 = k1; }
            b1 = c0; i1 = k0;
        } else if (c0 < b2) { b2 = c0; i2 = k0; }
        (void)c2; (void)k2;
    }
    if (sub == 0) {
        float d0 = fmaxf(b0, 1e-10f), d1 = fmaxf(b1, 1e-10f), d2 = fmaxf(b2, 1e-10f);
        float w0 = 1.0f / d0, w1 = 1.0f / d1, w2 = 1.0f / d2;
        float inv = 1.0f / (w0 + w1 + w2);
        g_idx[q * 3] = i0; g_idx[q * 3 + 1] = i1; g_idx[q * 3 + 2] = i2;
        g_w[q * 3] = w0 * inv; g_w[q * 3 + 1] = w1 * inv; g_w[q * 3 + 2] = w2 * inv;
    }
}

// ---------------------------------------------------------------------------
// Kernel 1b: convert feat2 -> fp16 (halves gather traffic in interp)
// ---------------------------------------------------------------------------
__global__ void f2h_kernel(const float* __restrict__ src) {
    const size_t i = ((size_t)blockIdx.x * 256 + threadIdx.x) * 4;
    float4 v = *(const float4*)(src + i);
    __half2 h0 = __floats2half2_rn(v.x, v.y);
    __half2 h1 = __floats2half2_rn(v.z, v.w);
    uint2 o;
    o.x = *(const uint32_t*)&h0;
    o.y = *(const uint32_t*)&h1;
    *(uint2*)(g_feat2h + i) = o;
}

// ---------------------------------------------------------------------------
// Kernel 2: interpolate (fp16 gather) + concat feat1 -> X (fp16)
// One warp per query; 1 uint4 (8 halfs) per lane per neighbor row.
// ---------------------------------------------------------------------------
__device__ __forceinline__ void to_h4(float4 o, __half* p) {
    __half2 h0 = __floats2half2_rn(o.x, o.y);
    __half2 h1 = __floats2half2_rn(o.z, o.w);
    *(__half2*)p = h0; *(__half2*)(p + 2) = h1;
}

__global__ void interp_kernel(const float* __restrict__ feat1) {
    const int q = blockIdx.x * 8 + (threadIdx.x >> 5);
    const int lane = threadIdx.x & 31;
    const int b = q >> 12;
    const int i0 = g_idx[q * 3], i1 = g_idx[q * 3 + 1], i2 = g_idx[q * 3 + 2];
    const float w0 = g_w[q * 3], w1 = g_w[q * 3 + 1], w2 = g_w[q * 3 + 2];

    const __half* f2 = g_feat2h + (size_t)b * N2 * C2;
    const uint4 v0 = ((const uint4*)(f2 + (size_t)i0 * C2))[lane];
    const uint4 v1 = ((const uint4*)(f2 + (size_t)i1 * C2))[lane];
    const uint4 v2 = ((const uint4*)(f2 + (size_t)i2 * C2))[lane];

    const __half2* h0 = (const __half2*)&v0;
    const __half2* h1 = (const __half2*)&v1;
    const __half2* h2 = (const __half2*)&v2;
    uint4 ov;
    __half2* oh = (__half2*)&ov;
#pragma unroll
    for (int k = 0; k < 4; k++) {
        float2 a = __half22float2(h0[k]);
        float2 d = __half22float2(h1[k]);
        float2 e = __half22float2(h2[k]);
        float ox = w0 * a.x + w1 * d.x + w2 * e.x;
        float oy = w0 * a.y + w1 * d.y + w2 * e.y;
        oh[k] = __floats2half2_rn(ox, oy);
    }
    __half* x = g_X + (size_t)q * DIN;
    ((uint4*)x)[lane] = ov;          // 32 lanes x 8 halfs = 256 = C2

    // feat1: 128 floats -> 32 lanes x 1 float4
    float4 f = ((const float4*)(feat1 + (size_t)q * C1))[lane];
    to_h4(f, x + C2 + lane * 4);
}

// ---------------------------------------------------------------------------
// Kernel 0: transpose W -> W^T fp16
// ---------------------------------------------------------------------------
__global__ void prep_w(const float* __restrict__ W1, const float* __restrict__ W2) {
    int i = blockIdx.x * 256 + threadIdx.x;
    if (i < DIN * DOUT) {
        int k = i / DOUT, n = i % DOUT;
        g_W1T[n * DIN + k] = __float2half(W1[i]);
    } else {
        int j = i - DIN * DOUT;
        if (j < DOUT * DOUT) {
            int k = j / DOUT, n = j % DOUT;
            g_W2T[n * DOUT + k] = __float2half(W2[j]);
        }
    }
}

// ---------------------------------------------------------------------------
// HGEMM: C[M,256] = relu(A[M,K] @ W + bias). CTA tile 128x128, BK=64,
// double-buffered cp.async, ldmatrix + mma.sync.m16n8k16, fp32 accumulate.
// ---------------------------------------------------------------------------
#define HGEMM_SMEM (2 * 32768)

template<int K, bool WRITE_H>
__global__ __launch_bounds__(256, 2) void hgemm(
    const __half* __restrict__ A, const __half* __restrict__ Bt,
    const float* __restrict__ bias,
    __half* __restrict__ outH, float* __restrict__ outF) {
    constexpr int NC = K / 64;
    extern __shared__ char smem[];
    const uint32_t sb = smem_u32(smem);
    const int tid = threadIdx.x;
    const int w = tid >> 5, lane = tid & 31;
    const int wy = w >> 2, wx = w & 3;
    const int mblk = blockIdx.y * 128, nblk = blockIdx.x * 128;

    const char* Abase = (const char*)(A + (size_t)mblk * K);
    const char* Bbase = (const char*)(Bt + (size_t)nblk * K);
    const int row_l = tid >> 3;
    const int ch_l = tid & 7;

    float acc[4][4][4];
#pragma unroll
    for (int i = 0; i < 4; i++)
#pragma unroll
        for (int j = 0; j < 4; j++)
#pragma unroll
            for (int k = 0; k < 4; k++) acc[i][j][k] = 0.0f;

    auto issue = [&](int c) {
        const uint32_t base = sb + (uint32_t)(c & 1) * 32768u;
        const char* ag = Abase + (size_t)c * 128;
        const char* bg = Bbase + (size_t)c * 128;
#pragma unroll
        for (int rr = 0; rr < 4; rr++) {
            const int row = row_l + rr * 32;
            const uint32_t off = (uint32_t)(row * 128 + ch_l * 16);
            const uint32_t d = base + SWZ(off);
            CP_ASYNC16(d, ag + (size_t)row * (K * 2) + ch_l * 16);
            CP_ASYNC16(d + 16384, bg + (size_t)row * (K * 2) + ch_l * 16);
        }
        CP_COMMIT();
    };

    issue(0);
#pragma unroll
    for (int c = 0; c < NC; c++) {
        if (c + 1 < NC) { issue(c + 1); CP_WAIT(1); }
        else            { CP_WAIT(0); }
        __syncthreads();
        const uint32_t abase = sb + (uint32_t)(c & 1) * 32768u;
        const uint32_t bbase = abase + 16384u;
#pragma unroll
        for (int ks = 0; ks < 4; ks++) {
            uint32_t af[4][4];
#pragma unroll
            for (int mt = 0; mt < 4; mt++) {
                const int row = wy * 64 + mt * 16 + ((lane >> 3) & 1) * 8 + (lane & 7);
                const int ch = ks * 2 + (lane >> 4);
                const uint32_t off = (uint32_t)(row * 128 + ch * 16);
                ldmatrix_x4(af[mt], abase + SWZ(off));
            }
            uint32_t bf[4][2];
#pragma unroll
            for (int p = 0; p < 2; p++) {
                const int t = lane >> 3;
                const int nrow = wx * 32 + (2 * p + (t >> 1)) * 8 + (lane & 7);
                const int ch = ks * 2 + (t & 1);
                const uint32_t off = (uint32_t)(nrow * 128 + ch * 16);
                uint32_t r[4];
                ldmatrix_x4(r, bbase + SWZ(off));
                bf[2 * p][0] = r[0]; bf[2 * p][1] = r[1];
                bf[2 * p + 1][0] = r[2]; bf[2 * p + 1][1] = r[3];
            }
#pragma unroll
            for (int mt = 0; mt < 4; mt++)
#pragma unroll
                for (int nt = 0; nt < 4; nt++)
                    mma16816(acc[mt][nt], af[mt], bf[nt]);
        }
        __syncthreads();
    }

#pragma unroll
    for (int mt = 0; mt < 4; mt++) {
#pragma unroll
        for (int nt = 0; nt < 4; nt++) {
            const int row0 = mblk + wy * 64 + mt * 16 + (lane >> 2);
            const int col = nblk + wx * 32 + nt * 8 + 2 * (lane & 3);
            const float bz0 = bias[col], bz1 = bias[col + 1];
            float v00 = fmaxf(acc[mt][nt][0] + bz0, 0.0f);
            float v01 = fmaxf(acc[mt][nt][1] + bz1, 0.0f);
            float v10 = fmaxf(acc[mt][nt][2] + bz0, 0.0f);
            float v11 = fmaxf(acc[mt][nt][3] + bz1, 0.0f);
            if constexpr (WRITE_H) {
                *(__half2*)(outH + (size_t)row0 * 256 + col) = __floats2half2_rn(v00, v01);
                *(__half2*)(outH + (size_t)(row0 + 8) * 256 + col) = __floats2half2_rn(v10, v11);
            } else {
                float2 o0; o0.x = v00; o0.y = v01;
                float2 o1; o1.x = v10; o1.y = v11;
                *(float2*)(outF + (size_t)row0 * 256 + col) = o0;
                *(float2*)(outF + (size_t)(row0 + 8) * 256 + col) = o1;
            }
        }
    }
}

// ---------------------------------------------------------------------------
extern "C" void kernel_launch(void* const* d_in, const int* in_sizes, int n_in,
                              void* d_out, int out_size) {
    const float* xyz1  = (const float*)d_in[0];
    const float* feat1 = (const float*)d_in[1];
    const float* xyz2  = (const float*)d_in[2];
    const float* feat2 = (const float*)d_in[3];
    const float* W1    = (const float*)d_in[4];
    const float* b1    = (const float*)d_in[5];
    const float* W2    = (const float*)d_in[6];
    const float* b2    = (const float*)d_in[7];
    float* out = (float*)d_out;

    __half *X, *H, *W1T, *W2T;
    cudaGetSymbolAddress((void**)&X, g_X);
    cudaGetSymbolAddress((void**)&H, g_H);
    cudaGetSymbolAddress((void**)&W1T, g_W1T);
    cudaGetSymbolAddress((void**)&W2T, g_W2T);

    cudaFuncSetAttribute((const void*)hgemm<DIN, true>,
                         cudaFuncAttributeMaxDynamicSharedMemorySize, HGEMM_SMEM);
    cudaFuncSetAttribute((const void*)hgemm<DOUT, false>,
                         cudaFuncAttributeMaxDynamicSharedMemorySize, HGEMM_SMEM);

    prep_w<<<(DIN * DOUT + DOUT * DOUT) / 256, 256>>>(W1, W2);
    f2h_kernel<<<(BB * N2 * C2) / 1024, 256>>>(feat2);
    knn_kernel<<<NQ / 64, 256>>>(xyz1, xyz2);
    interp_kernel<<<NQ / 8, 256>>>(feat1);

    dim3 grid(DOUT / 128, NQ / 128);
    hgemm<DIN, true><<<grid, 256, HGEMM_SMEM>>>(X, W1T, b1, H, nullptr);
    hgemm<DOUT, false><<<grid, 256, HGEMM_SMEM>>>(H, W2T, b2, nullptr, out);
}